// round 2
// baseline (speedup 1.0000x reference)
#include <cuda_runtime.h>
#include <math.h>

// Problem constants
constexpr int N_   = 50000;
constexpr int E_   = 800000;
constexpr int R_   = 3;
constexpr int IN_  = 128;
constexpr int HID_ = 128;
constexpr int D_   = 384;
constexpr int H_   = 8;
constexpr int O_   = 16;
constexpr int HO_  = 128;   // H*O
constexpr int OUT_ = 64;
constexpr int L_   = 4;
constexpr float BN_EPS = 1e-5f;

// ------------------------------------------------------------------
// Static device scratch (no allocations allowed)
// ------------------------------------------------------------------
__device__ float g_x   [(size_t)N_ * D_];    // embedding output (residual)
__device__ float g_h   [(size_t)N_ * D_];    // current features
__device__ float g_hnew[(size_t)N_ * D_];    // concat accumulator
__device__ float g_hW  [(size_t)N_ * HO_];   // per-relation transformed features
__device__ float g_hid [(size_t)N_ * HID_];  // MLP hidden (pre-BN)
__device__ float g_hid2[(size_t)N_ * HID_];  // MLP hidden (post BN+ReLU)
__device__ float g_el  [(size_t)N_ * H_];
__device__ float g_er  [(size_t)N_ * H_];
__device__ float g_ee  [(size_t)E_ * H_];    // exp(s) per edge
__device__ float g_den [(size_t)N_ * H_];    // softmax denominators
__device__ float g_stats[2 * HID_];          // BN sums [sum, sumsq]
__device__ float g_mean[HID_];
__device__ float g_rstd[HID_];
__device__ unsigned g_smax;                  // order-encoded global max

// ------------------------------------------------------------------
// Helpers
// ------------------------------------------------------------------
__device__ __forceinline__ unsigned fenc(float f) {
    unsigned b = __float_as_uint(f);
    return (b & 0x80000000u) ? ~b : (b | 0x80000000u);
}
__device__ __forceinline__ float fdec(unsigned u) {
    unsigned b = (u & 0x80000000u) ? (u & 0x7FFFFFFFu) : ~u;
    return __uint_as_float(b);
}
__device__ __forceinline__ float lrelu(float v, float a) {
    return v > 0.f ? v : a * v;
}

// ------------------------------------------------------------------
// Tiled fp32 GEMM: C[M,Nc] = A[M,K] @ B[K,Nc]
// BM=64, BN=64, BK=16, 256 threads, 4x4 per thread.
// Nc and K must be multiples of 64 / 16 respectively (true for all calls).
// ------------------------------------------------------------------
__global__ void gemm_kernel(const float* __restrict__ A,
                            const float* __restrict__ B,
                            float* __restrict__ C,
                            int M, int Nc, int K) {
    constexpr int BM = 64, BN = 64, BK = 16;
    __shared__ float As[BK][BM];
    __shared__ float Bs[BK][BN];

    const int tid = threadIdx.x;
    const int block_row = blockIdx.y * BM;
    const int block_col = blockIdx.x * BN;
    const int tr = tid / 16;   // 0..15
    const int tc = tid % 16;   // 0..15

    float acc[4][4] = {};

    for (int k0 = 0; k0 < K; k0 += BK) {
        // Load A tile (BM x BK), transposed into As[BK][BM]
        #pragma unroll
        for (int i = tid; i < BM * BK; i += 256) {
            int r = i / BK, c = i % BK;
            int gr = block_row + r;
            As[c][r] = (gr < M) ? A[(size_t)gr * K + (k0 + c)] : 0.f;
        }
        // Load B tile (BK x BN)
        #pragma unroll
        for (int i = tid; i < BK * BN; i += 256) {
            int r = i / BN, c = i % BN;
            Bs[r][c] = B[(size_t)(k0 + r) * Nc + (block_col + c)];
        }
        __syncthreads();

        #pragma unroll
        for (int kk = 0; kk < BK; kk++) {
            float a[4], b[4];
            #pragma unroll
            for (int i = 0; i < 4; i++) a[i] = As[kk][tr * 4 + i];
            #pragma unroll
            for (int j = 0; j < 4; j++) b[j] = Bs[kk][tc * 4 + j];
            #pragma unroll
            for (int i = 0; i < 4; i++)
                #pragma unroll
                for (int j = 0; j < 4; j++)
                    acc[i][j] += a[i] * b[j];
        }
        __syncthreads();
    }

    #pragma unroll
    for (int i = 0; i < 4; i++) {
        int gr = block_row + tr * 4 + i;
        if (gr < M) {
            #pragma unroll
            for (int j = 0; j < 4; j++)
                C[(size_t)gr * Nc + block_col + tc * 4 + j] = acc[i][j];
        }
    }
}

// ------------------------------------------------------------------
// BN: stage 1 — per-block partial sums, 128 threads (one per column)
// ------------------------------------------------------------------
__global__ void bn_partial_kernel(const float* __restrict__ hid, int M) {
    const int c = threadIdx.x;   // 0..127
    const int rows_per_block = (M + gridDim.x - 1) / gridDim.x;
    const int r0 = blockIdx.x * rows_per_block;
    const int r1 = min(M, r0 + rows_per_block);
    float s = 0.f, s2 = 0.f;
    for (int r = r0; r < r1; r++) {
        float v = hid[(size_t)r * HID_ + c];
        s += v;
        s2 += v * v;
    }
    atomicAdd(&g_stats[c], s);
    atomicAdd(&g_stats[HID_ + c], s2);
}

// BN: stage 2 — finalize mean/rstd
__global__ void bn_finalize_kernel(int M) {
    const int c = threadIdx.x;
    float mu = g_stats[c] / (float)M;
    float var = g_stats[HID_ + c] / (float)M - mu * mu;
    g_mean[c] = mu;
    g_rstd[c] = rsqrtf(var + BN_EPS);
}

// BN apply + ReLU
__global__ void bn_relu_kernel(const float* __restrict__ hid,
                               const float* __restrict__ gamma,
                               const float* __restrict__ beta,
                               float* __restrict__ out, int total) {
    int i = blockIdx.x * blockDim.x + threadIdx.x;
    if (i >= total) return;
    int c = i & (HID_ - 1);
    float v = (hid[i] - g_mean[c]) * g_rstd[c] * gamma[c] + beta[c];
    out[i] = v > 0.f ? v : 0.f;
}

// ------------------------------------------------------------------
// Attention coefficients: el[n,h] = sum_o hW[n,h*16+o]*al[h,o]
// One thread per (n,h).
// ------------------------------------------------------------------
__global__ void attn_coef_kernel(const float* __restrict__ hW,
                                 const float* __restrict__ al,
                                 const float* __restrict__ ar) {
    int i = blockIdx.x * blockDim.x + threadIdx.x;
    if (i >= N_ * H_) return;
    int n = i >> 3, h = i & 7;
    const float* row = hW + (size_t)n * HO_ + h * O_;
    const float* wl = al + h * O_;
    const float* wr = ar + h * O_;
    float sl = 0.f, sr = 0.f;
    #pragma unroll
    for (int o = 0; o < O_; o++) {
        float v = row[o];
        sl += v * wl[o];
        sr += v * wr[o];
    }
    g_el[i] = sl;
    g_er[i] = sr;
}

// ------------------------------------------------------------------
// Edge pass 1: global max of leaky_relu(el[src]+er[trg], 0.2)
// ------------------------------------------------------------------
__global__ void edge_max_kernel(const int* __restrict__ src,
                                const int* __restrict__ trg) {
    int e = blockIdx.x * blockDim.x + threadIdx.x;
    float m = -INFINITY;
    if (e < E_) {
        int s = src[e], t = trg[e];
        const float4* el4 = (const float4*)g_el;
        const float4* er4 = (const float4*)g_er;
        float4 a0 = el4[s * 2], a1 = el4[s * 2 + 1];
        float4 b0 = er4[t * 2], b1 = er4[t * 2 + 1];
        float v;
        v = lrelu(a0.x + b0.x, 0.2f); m = fmaxf(m, v);
        v = lrelu(a0.y + b0.y, 0.2f); m = fmaxf(m, v);
        v = lrelu(a0.z + b0.z, 0.2f); m = fmaxf(m, v);
        v = lrelu(a0.w + b0.w, 0.2f); m = fmaxf(m, v);
        v = lrelu(a1.x + b1.x, 0.2f); m = fmaxf(m, v);
        v = lrelu(a1.y + b1.y, 0.2f); m = fmaxf(m, v);
        v = lrelu(a1.z + b1.z, 0.2f); m = fmaxf(m, v);
        v = lrelu(a1.w + b1.w, 0.2f); m = fmaxf(m, v);
    }
    #pragma unroll
    for (int o = 16; o > 0; o >>= 1)
        m = fmaxf(m, __shfl_xor_sync(0xffffffffu, m, o));
    if ((threadIdx.x & 31) == 0)
        atomicMax(&g_smax, fenc(m));
}

// ------------------------------------------------------------------
// Edge pass 2: e = exp(s - smax), accumulate denom per target
// ------------------------------------------------------------------
__global__ void edge_exp_kernel(const int* __restrict__ src,
                                const int* __restrict__ trg) {
    int e = blockIdx.x * blockDim.x + threadIdx.x;
    if (e >= E_) return;
    int s = src[e], t = trg[e];
    float smax = fdec(g_smax);
    const float* el = g_el + (size_t)s * H_;
    const float* er = g_er + (size_t)t * H_;
    float* ee = g_ee + (size_t)e * H_;
    #pragma unroll
    for (int h = 0; h < H_; h++) {
        float v = lrelu(el[h] + er[h], 0.2f);
        float ex = expf(v - smax);
        ee[h] = ex;
        atomicAdd(&g_den[(size_t)t * H_ + h], ex);
    }
}

// ------------------------------------------------------------------
// Edge pass 3: scatter msg = hW[src] * alpha into h_new[trg]
// One warp per edge; lane handles channels lane, lane+32, lane+64, lane+96.
// ------------------------------------------------------------------
__global__ void edge_scatter_kernel(const int* __restrict__ src,
                                    const int* __restrict__ trg,
                                    const float* __restrict__ hW,
                                    int col_off) {
    int idx = blockIdx.x * blockDim.x + threadIdx.x;
    int e = idx >> 5;
    int lane = idx & 31;
    if (e >= E_) return;
    int s = src[e], t = trg[e];
    float a = 0.f;
    if (lane < H_)
        a = g_ee[(size_t)e * H_ + lane] / (g_den[(size_t)t * H_ + lane] + 1e-16f);
    const float* hrow = hW + (size_t)s * HO_;
    float* orow = g_hnew + (size_t)t * D_ + col_off;
    #pragma unroll
    for (int j = 0; j < 4; j++) {
        int c = lane + 32 * j;
        float alpha = __shfl_sync(0xffffffffu, a, c >> 4);
        atomicAdd(&orow[c], hrow[c] * alpha);
    }
}

// ------------------------------------------------------------------
// Layer combine: h = leaky_relu(h_new, 0.01) + x
// ------------------------------------------------------------------
__global__ void combine_kernel(int total) {
    int i = blockIdx.x * blockDim.x + threadIdx.x;
    if (i >= total) return;
    g_h[i] = lrelu(g_hnew[i], 0.01f) + g_x[i];
}

// ------------------------------------------------------------------
// Host launch
// ------------------------------------------------------------------
static void launch_gemm(const float* A, const float* B, float* C,
                        int M, int Nc, int K) {
    dim3 grid(Nc / 64, (M + 63) / 64);
    gemm_kernel<<<grid, 256>>>(A, B, C, M, Nc, K);
}

extern "C" void kernel_launch(void* const* d_in, const int* in_sizes, int n_in,
                              void* d_out, int out_size) {
    const float* inputs = (const float*)d_in[0];
    const int*   edges  = (const int*)  d_in[1];
    const float* W_emb1 = (const float*)d_in[2];
    const float* W_emb2 = (const float*)d_in[3];
    const float* g_emb  = (const float*)d_in[4];
    const float* b_emb  = (const float*)d_in[5];
    const float* Wg     = (const float*)d_in[6];
    const float* al     = (const float*)d_in[7];
    const float* ar     = (const float*)d_in[8];
    const float* W_d1   = (const float*)d_in[9];
    const float* W_d2   = (const float*)d_in[10];
    const float* g_d    = (const float*)d_in[11];
    const float* b_d    = (const float*)d_in[12];
    float* out = (float*)d_out;

    // Resolve scratch symbol addresses (host API, not stream-ordered: capture-safe)
    float *px, *ph, *phnew, *phW, *phid, *phid2, *pstats, *pden;
    unsigned* psmax;
    cudaGetSymbolAddress((void**)&px,    g_x);
    cudaGetSymbolAddress((void**)&ph,    g_h);
    cudaGetSymbolAddress((void**)&phnew, g_hnew);
    cudaGetSymbolAddress((void**)&phW,   g_hW);
    cudaGetSymbolAddress((void**)&phid,  g_hid);
    cudaGetSymbolAddress((void**)&phid2, g_hid2);
    cudaGetSymbolAddress((void**)&pstats,g_stats);
    cudaGetSymbolAddress((void**)&pden,  g_den);
    cudaGetSymbolAddress((void**)&psmax, g_smax);

    const int THR = 256;
    const int nh_blocks  = (N_ * H_ + THR - 1) / THR;      // attn coef
    const int e_blocks   = (E_ + THR - 1) / THR;           // per-edge
    const int ew_blocks  = ((E_ * 32) + THR - 1) / THR;    // warp-per-edge
    const int nd_blocks  = (N_ * D_ + THR - 1) / THR;      // elementwise [N,D]
    const int nhid_blocks= (N_ * HID_ + THR - 1) / THR;    // elementwise [N,HID]

    // ---------------- Encoder MLP ----------------
    launch_gemm(inputs, W_emb1, phid, N_, HID_, IN_);
    cudaMemsetAsync(pstats, 0, 2 * HID_ * sizeof(float), 0);
    bn_partial_kernel<<<256, HID_>>>(phid, N_);
    bn_finalize_kernel<<<1, HID_>>>(N_);
    bn_relu_kernel<<<nhid_blocks, THR>>>(phid, g_emb, b_emb, phid2, N_ * HID_);
    launch_gemm(phid2, W_emb2, px, N_, D_, HID_);

    // h = x
    cudaMemcpyAsync(ph, px, (size_t)N_ * D_ * sizeof(float),
                    cudaMemcpyDeviceToDevice, 0);

    // ---------------- GAT layers ----------------
    for (int l = 0; l < L_; l++) {
        cudaMemsetAsync(phnew, 0, (size_t)N_ * D_ * sizeof(float), 0);
        for (int r = 0; r < R_; r++) {
            const int* src = edges + ((size_t)r * 2 + 0) * E_;
            const int* trg = edges + ((size_t)r * 2 + 1) * E_;
            const float* Wg_lr = Wg + ((size_t)(l * R_ + r)) * D_ * HO_;
            const float* al_lr = al + (size_t)(l * R_ + r) * HO_;
            const float* ar_lr = ar + (size_t)(l * R_ + r) * HO_;

            launch_gemm(ph, Wg_lr, phW, N_, HO_, D_);
            attn_coef_kernel<<<nh_blocks, THR>>>(phW, al_lr, ar_lr);

            cudaMemsetAsync(psmax, 0, sizeof(unsigned), 0);
            cudaMemsetAsync(pden, 0, (size_t)N_ * H_ * sizeof(float), 0);

            edge_max_kernel<<<e_blocks, THR>>>(src, trg);
            edge_exp_kernel<<<e_blocks, THR>>>(src, trg);
            edge_scatter_kernel<<<ew_blocks, THR>>>(src, trg, phW, r * HO_);
        }
        combine_kernel<<<nd_blocks, THR>>>(N_ * D_);
    }

    // ---------------- Decoder MLP ----------------
    launch_gemm(ph, W_d1, phid, N_, HID_, D_);
    cudaMemsetAsync(pstats, 0, 2 * HID_ * sizeof(float), 0);
    bn_partial_kernel<<<256, HID_>>>(phid, N_);
    bn_finalize_kernel<<<1, HID_>>>(N_);
    bn_relu_kernel<<<nhid_blocks, THR>>>(phid, g_d, b_d, phid2, N_ * HID_);
    launch_gemm(phid2, W_d2, out, N_, OUT_, HID_);
}

// round 3
// speedup vs baseline: 1.0015x; 1.0015x over previous
#include <cuda_runtime.h>
#include <math.h>

// Problem constants
constexpr int N_   = 50000;
constexpr int E_   = 800000;
constexpr int R_   = 3;
constexpr int IN_  = 128;
constexpr int HID_ = 128;
constexpr int D_   = 384;
constexpr int H_   = 8;
constexpr int O_   = 16;
constexpr int HO_  = 128;   // H*O
constexpr int OUT_ = 64;
constexpr int L_   = 4;
constexpr float BN_EPS = 1e-5f;

// ------------------------------------------------------------------
// Static device scratch (no allocations allowed)
// ------------------------------------------------------------------
__device__ float g_x   [(size_t)N_ * D_];    // embedding output (residual)
__device__ float g_h   [(size_t)N_ * D_];    // current features
__device__ float g_hnew[(size_t)N_ * D_];    // concat accumulator
__device__ float g_hW  [(size_t)N_ * HO_];   // per-relation transformed features
__device__ float g_hid [(size_t)N_ * HID_];  // MLP hidden (pre-BN)
__device__ float g_hid2[(size_t)N_ * HID_];  // MLP hidden (post BN+ReLU)
__device__ float g_el  [(size_t)N_ * H_];
__device__ float g_er  [(size_t)N_ * H_];
__device__ float g_ee  [(size_t)E_ * H_];    // exp(s) per edge
__device__ float g_den [(size_t)N_ * H_];    // softmax denominators
__device__ float g_stats[2 * HID_];          // BN sums [sum, sumsq]
__device__ float g_mean[HID_];
__device__ float g_rstd[HID_];
__device__ unsigned g_smax;                  // order-encoded global max

// ------------------------------------------------------------------
// Helpers
// ------------------------------------------------------------------
__device__ __forceinline__ unsigned fenc(float f) {
    unsigned b = __float_as_uint(f);
    return (b & 0x80000000u) ? ~b : (b | 0x80000000u);
}
__device__ __forceinline__ float fdec(unsigned u) {
    unsigned b = (u & 0x80000000u) ? (u & 0x7FFFFFFFu) : ~u;
    return __uint_as_float(b);
}
__device__ __forceinline__ float lrelu(float v, float a) {
    return v > 0.f ? v : a * v;
}

// ------------------------------------------------------------------
// Tiled fp32 GEMM: C[M,Nc] = A[M,K] @ B[K,Nc]
// BM=64, BN=64, BK=16, 256 threads, 4x4 per thread.
// Nc and K must be multiples of 64 / 16 respectively (true for all calls).
// ------------------------------------------------------------------
__global__ void gemm_kernel(const float* __restrict__ A,
                            const float* __restrict__ B,
                            float* __restrict__ C,
                            int M, int Nc, int K) {
    constexpr int BM = 64, BN = 64, BK = 16;
    __shared__ float As[BK][BM];
    __shared__ float Bs[BK][BN];

    const int tid = threadIdx.x;
    const int block_row = blockIdx.y * BM;
    const int block_col = blockIdx.x * BN;
    const int tr = tid / 16;   // 0..15
    const int tc = tid % 16;   // 0..15

    float acc[4][4] = {};

    for (int k0 = 0; k0 < K; k0 += BK) {
        // Load A tile (BM x BK), transposed into As[BK][BM]
        #pragma unroll
        for (int i = tid; i < BM * BK; i += 256) {
            int r = i / BK, c = i % BK;
            int gr = block_row + r;
            As[c][r] = (gr < M) ? A[(size_t)gr * K + (k0 + c)] : 0.f;
        }
        // Load B tile (BK x BN)
        #pragma unroll
        for (int i = tid; i < BK * BN; i += 256) {
            int r = i / BN, c = i % BN;
            Bs[r][c] = B[(size_t)(k0 + r) * Nc + (block_col + c)];
        }
        __syncthreads();

        #pragma unroll
        for (int kk = 0; kk < BK; kk++) {
            float a[4], b[4];
            #pragma unroll
            for (int i = 0; i < 4; i++) a[i] = As[kk][tr * 4 + i];
            #pragma unroll
            for (int j = 0; j < 4; j++) b[j] = Bs[kk][tc * 4 + j];
            #pragma unroll
            for (int i = 0; i < 4; i++)
                #pragma unroll
                for (int j = 0; j < 4; j++)
                    acc[i][j] += a[i] * b[j];
        }
        __syncthreads();
    }

    #pragma unroll
    for (int i = 0; i < 4; i++) {
        int gr = block_row + tr * 4 + i;
        if (gr < M) {
            #pragma unroll
            for (int j = 0; j < 4; j++)
                C[(size_t)gr * Nc + block_col + tc * 4 + j] = acc[i][j];
        }
    }
}

// ------------------------------------------------------------------
// BN: stage 1 — per-block partial sums, 128 threads (one per column)
// ------------------------------------------------------------------
__global__ void bn_partial_kernel(const float* __restrict__ hid, int M) {
    const int c = threadIdx.x;   // 0..127
    const int rows_per_block = (M + gridDim.x - 1) / gridDim.x;
    const int r0 = blockIdx.x * rows_per_block;
    const int r1 = min(M, r0 + rows_per_block);
    float s = 0.f, s2 = 0.f;
    for (int r = r0; r < r1; r++) {
        float v = hid[(size_t)r * HID_ + c];
        s += v;
        s2 += v * v;
    }
    atomicAdd(&g_stats[c], s);
    atomicAdd(&g_stats[HID_ + c], s2);
}

// BN: stage 2 — finalize mean/rstd
__global__ void bn_finalize_kernel(int M) {
    const int c = threadIdx.x;
    float mu = g_stats[c] / (float)M;
    float var = g_stats[HID_ + c] / (float)M - mu * mu;
    g_mean[c] = mu;
    g_rstd[c] = rsqrtf(var + BN_EPS);
}

// BN apply + ReLU
__global__ void bn_relu_kernel(const float* __restrict__ hid,
                               const float* __restrict__ gamma,
                               const float* __restrict__ beta,
                               float* __restrict__ out, int total) {
    int i = blockIdx.x * blockDim.x + threadIdx.x;
    if (i >= total) return;
    int c = i & (HID_ - 1);
    float v = (hid[i] - g_mean[c]) * g_rstd[c] * gamma[c] + beta[c];
    out[i] = v > 0.f ? v : 0.f;
}

// ------------------------------------------------------------------
// Attention coefficients: el[n,h] = sum_o hW[n,h*16+o]*al[h,o]
// One thread per (n,h).
// ------------------------------------------------------------------
__global__ void attn_coef_kernel(const float* __restrict__ hW,
                                 const float* __restrict__ al,
                                 const float* __restrict__ ar) {
    int i = blockIdx.x * blockDim.x + threadIdx.x;
    if (i >= N_ * H_) return;
    int n = i >> 3, h = i & 7;
    const float* row = hW + (size_t)n * HO_ + h * O_;
    const float* wl = al + h * O_;
    const float* wr = ar + h * O_;
    float sl = 0.f, sr = 0.f;
    #pragma unroll
    for (int o = 0; o < O_; o++) {
        float v = row[o];
        sl += v * wl[o];
        sr += v * wr[o];
    }
    g_el[i] = sl;
    g_er[i] = sr;
}

// ------------------------------------------------------------------
// Edge pass 1: global max of leaky_relu(el[src]+er[trg], 0.2)
// ------------------------------------------------------------------
__global__ void edge_max_kernel(const int* __restrict__ src,
                                const int* __restrict__ trg) {
    int e = blockIdx.x * blockDim.x + threadIdx.x;
    float m = -INFINITY;
    if (e < E_) {
        int s = src[e], t = trg[e];
        const float4* el4 = (const float4*)g_el;
        const float4* er4 = (const float4*)g_er;
        float4 a0 = el4[s * 2], a1 = el4[s * 2 + 1];
        float4 b0 = er4[t * 2], b1 = er4[t * 2 + 1];
        float v;
        v = lrelu(a0.x + b0.x, 0.2f); m = fmaxf(m, v);
        v = lrelu(a0.y + b0.y, 0.2f); m = fmaxf(m, v);
        v = lrelu(a0.z + b0.z, 0.2f); m = fmaxf(m, v);
        v = lrelu(a0.w + b0.w, 0.2f); m = fmaxf(m, v);
        v = lrelu(a1.x + b1.x, 0.2f); m = fmaxf(m, v);
        v = lrelu(a1.y + b1.y, 0.2f); m = fmaxf(m, v);
        v = lrelu(a1.z + b1.z, 0.2f); m = fmaxf(m, v);
        v = lrelu(a1.w + b1.w, 0.2f); m = fmaxf(m, v);
    }
    #pragma unroll
    for (int o = 16; o > 0; o >>= 1)
        m = fmaxf(m, __shfl_xor_sync(0xffffffffu, m, o));
    if ((threadIdx.x & 31) == 0)
        atomicMax(&g_smax, fenc(m));
}

// ------------------------------------------------------------------
// Edge pass 2: e = exp(s - smax), accumulate denom per target
// ------------------------------------------------------------------
__global__ void edge_exp_kernel(const int* __restrict__ src,
                                const int* __restrict__ trg) {
    int e = blockIdx.x * blockDim.x + threadIdx.x;
    if (e >= E_) return;
    int s = src[e], t = trg[e];
    float smax = fdec(g_smax);
    const float* el = g_el + (size_t)s * H_;
    const float* er = g_er + (size_t)t * H_;
    float* ee = g_ee + (size_t)e * H_;
    #pragma unroll
    for (int h = 0; h < H_; h++) {
        float v = lrelu(el[h] + er[h], 0.2f);
        float ex = expf(v - smax);
        ee[h] = ex;
        atomicAdd(&g_den[(size_t)t * H_ + h], ex);
    }
}

// ------------------------------------------------------------------
// Edge pass 3: scatter msg = hW[src] * alpha into h_new[trg]
// One warp per edge; lane handles channels lane, lane+32, lane+64, lane+96.
// ------------------------------------------------------------------
__global__ void edge_scatter_kernel(const int* __restrict__ src,
                                    const int* __restrict__ trg,
                                    const float* __restrict__ hW,
                                    int col_off) {
    int idx = blockIdx.x * blockDim.x + threadIdx.x;
    int e = idx >> 5;
    int lane = idx & 31;
    if (e >= E_) return;
    int s = src[e], t = trg[e];
    float a = 0.f;
    if (lane < H_)
        a = g_ee[(size_t)e * H_ + lane] / (g_den[(size_t)t * H_ + lane] + 1e-16f);
    const float* hrow = hW + (size_t)s * HO_;
    float* orow = g_hnew + (size_t)t * D_ + col_off;
    #pragma unroll
    for (int j = 0; j < 4; j++) {
        int c = lane + 32 * j;
        float alpha = __shfl_sync(0xffffffffu, a, c >> 4);
        atomicAdd(&orow[c], hrow[c] * alpha);
    }
}

// ------------------------------------------------------------------
// Layer combine: h = leaky_relu(h_new, 0.01) + x
// ------------------------------------------------------------------
__global__ void combine_kernel(int total) {
    int i = blockIdx.x * blockDim.x + threadIdx.x;
    if (i >= total) return;
    g_h[i] = lrelu(g_hnew[i], 0.01f) + g_x[i];
}

// ------------------------------------------------------------------
// Host launch
// ------------------------------------------------------------------
static void launch_gemm(const float* A, const float* B, float* C,
                        int M, int Nc, int K) {
    dim3 grid(Nc / 64, (M + 63) / 64);
    gemm_kernel<<<grid, 256>>>(A, B, C, M, Nc, K);
}

extern "C" void kernel_launch(void* const* d_in, const int* in_sizes, int n_in,
                              void* d_out, int out_size) {
    const float* inputs = (const float*)d_in[0];
    const int*   edges  = (const int*)  d_in[1];
    const float* W_emb1 = (const float*)d_in[2];
    const float* W_emb2 = (const float*)d_in[3];
    const float* g_emb  = (const float*)d_in[4];
    const float* b_emb  = (const float*)d_in[5];
    const float* Wg     = (const float*)d_in[6];
    const float* al     = (const float*)d_in[7];
    const float* ar     = (const float*)d_in[8];
    const float* W_d1   = (const float*)d_in[9];
    const float* W_d2   = (const float*)d_in[10];
    const float* g_d    = (const float*)d_in[11];
    const float* b_d    = (const float*)d_in[12];
    float* out = (float*)d_out;

    // Resolve scratch symbol addresses (host API, not stream-ordered: capture-safe)
    float *px, *ph, *phnew, *phW, *phid, *phid2, *pstats, *pden;
    unsigned* psmax;
    cudaGetSymbolAddress((void**)&px,    g_x);
    cudaGetSymbolAddress((void**)&ph,    g_h);
    cudaGetSymbolAddress((void**)&phnew, g_hnew);
    cudaGetSymbolAddress((void**)&phW,   g_hW);
    cudaGetSymbolAddress((void**)&phid,  g_hid);
    cudaGetSymbolAddress((void**)&phid2, g_hid2);
    cudaGetSymbolAddress((void**)&pstats,g_stats);
    cudaGetSymbolAddress((void**)&pden,  g_den);
    cudaGetSymbolAddress((void**)&psmax, g_smax);

    const int THR = 256;
    const int nh_blocks  = (N_ * H_ + THR - 1) / THR;      // attn coef
    const int e_blocks   = (E_ + THR - 1) / THR;           // per-edge
    const int ew_blocks  = ((E_ * 32) + THR - 1) / THR;    // warp-per-edge
    const int nd_blocks  = (N_ * D_ + THR - 1) / THR;      // elementwise [N,D]
    const int nhid_blocks= (N_ * HID_ + THR - 1) / THR;    // elementwise [N,HID]

    // ---------------- Encoder MLP ----------------
    launch_gemm(inputs, W_emb1, phid, N_, HID_, IN_);
    cudaMemsetAsync(pstats, 0, 2 * HID_ * sizeof(float), 0);
    bn_partial_kernel<<<256, HID_>>>(phid, N_);
    bn_finalize_kernel<<<1, HID_>>>(N_);
    bn_relu_kernel<<<nhid_blocks, THR>>>(phid, g_emb, b_emb, phid2, N_ * HID_);
    launch_gemm(phid2, W_emb2, px, N_, D_, HID_);

    // h = x
    cudaMemcpyAsync(ph, px, (size_t)N_ * D_ * sizeof(float),
                    cudaMemcpyDeviceToDevice, 0);

    // ---------------- GAT layers ----------------
    for (int l = 0; l < L_; l++) {
        cudaMemsetAsync(phnew, 0, (size_t)N_ * D_ * sizeof(float), 0);
        for (int r = 0; r < R_; r++) {
            const int* src = edges + ((size_t)r * 2 + 0) * E_;
            const int* trg = edges + ((size_t)r * 2 + 1) * E_;
            const float* Wg_lr = Wg + ((size_t)(l * R_ + r)) * D_ * HO_;
            const float* al_lr = al + (size_t)(l * R_ + r) * HO_;
            const float* ar_lr = ar + (size_t)(l * R_ + r) * HO_;

            launch_gemm(ph, Wg_lr, phW, N_, HO_, D_);
            attn_coef_kernel<<<nh_blocks, THR>>>(phW, al_lr, ar_lr);

            cudaMemsetAsync(psmax, 0, sizeof(unsigned), 0);
            cudaMemsetAsync(pden, 0, (size_t)N_ * H_ * sizeof(float), 0);

            edge_max_kernel<<<e_blocks, THR>>>(src, trg);
            edge_exp_kernel<<<e_blocks, THR>>>(src, trg);
            edge_scatter_kernel<<<ew_blocks, THR>>>(src, trg, phW, r * HO_);
        }
        combine_kernel<<<nd_blocks, THR>>>(N_ * D_);
    }

    // ---------------- Decoder MLP ----------------
    launch_gemm(ph, W_d1, phid, N_, HID_, D_);
    cudaMemsetAsync(pstats, 0, 2 * HID_ * sizeof(float), 0);
    bn_partial_kernel<<<256, HID_>>>(phid, N_);
    bn_finalize_kernel<<<1, HID_>>>(N_);
    bn_relu_kernel<<<nhid_blocks, THR>>>(phid, g_d, b_d, phid2, N_ * HID_);
    launch_gemm(phid2, W_d2, out, N_, OUT_, HID_);
}